// round 5
// baseline (speedup 1.0000x reference)
#include <cuda_runtime.h>
#include <stdint.h>

// Attention: B=256,H=32,S=16,D=64. scale=1/sqrt(8). +ones mask (cancels in softmax).
// Dropout p=0.3 replicating jax.random.bernoulli(jax.random.key(42), 0.7, (B,H,16,16))
// under the PARTITIONABLE threefry scheme (jax_threefry_partitionable, default):
//   counts = iota(uint64, N);  bits1,bits2 = threefry2x32(key=(0,42), hi(counts)=0, lo(counts)=i)
//   bits[i] = bits1 ^ bits2                      <-- XOR of BOTH output words (32-bit path)
//   uniform = bitcast((bits>>9)|0x3f800000)-1 ;  keep = uniform < 0.7f.

#define NHEADS      8192
#define HALF_HEADS  4096
#define HEAD_ELEMS  1024        // 16*64
#define STRK        68          // padded k stride (floats) for conflict-light LDS.128

__device__ __forceinline__ uint32_t threefry2x32_xor_k042(uint32_t x0, uint32_t x1) {
    const uint32_t k0 = 0u;
    const uint32_t k1 = 42u;
    const uint32_t k2 = 0x1BD11BDAu ^ k0 ^ k1;
    x0 += k0; x1 += k1;
#define TF_R(R) { x0 += x1; x1 = __funnelshift_l(x1, x1, (R)); x1 ^= x0; }
    TF_R(13) TF_R(15) TF_R(26) TF_R(6)
    x0 += k1; x1 += k2 + 1u;
    TF_R(17) TF_R(29) TF_R(16) TF_R(24)
    x0 += k2; x1 += k0 + 2u;
    TF_R(13) TF_R(15) TF_R(26) TF_R(6)
    x0 += k0; x1 += k1 + 3u;
    TF_R(17) TF_R(29) TF_R(16) TF_R(24)
    x0 += k1; x1 += k2 + 4u;
    TF_R(13) TF_R(15) TF_R(26) TF_R(6)
    x0 += k2; x1 += k0 + 5u;     // full final key injection (both words needed)
#undef TF_R
    return x0 ^ x1;              // 32-bit partitionable path: out0 XOR out1
}

__device__ __forceinline__ float tf_uniform(uint32_t bits) {
    return __uint_as_float((bits >> 9) | 0x3f800000u) - 1.0f;
}

__global__ __launch_bounds__(256)
void attn_drop_kernel(const float* __restrict__ q,
                      const float* __restrict__ k,
                      const float* __restrict__ v,
                      float* __restrict__ out) {
    __shared__ float qs[2][16 * 64];
    __shared__ float ks[2][16 * STRK];
    __shared__ float vs[2][16 * 64];
    __shared__ float ps[2][16 * 16];

    const int tid = threadIdx.x;
    const int h0  = blockIdx.x;            // head A; head B = h0 + 4096
    const int lr  = tid >> 4;              // 0..15
    const int lc4 = (tid & 15) * 4;        // 0,4,...,60

    // ---- Load q,k,v tiles for both heads (fully coalesced float4) ----
    #pragma unroll
    for (int hh = 0; hh < 2; hh++) {
        const int base = (h0 + hh * HALF_HEADS) * HEAD_ELEMS;
        float4 qv = *reinterpret_cast<const float4*>(q + base + tid * 4);
        float4 kv = *reinterpret_cast<const float4*>(k + base + tid * 4);
        float4 vv = *reinterpret_cast<const float4*>(v + base + tid * 4);
        *reinterpret_cast<float4*>(&qs[hh][lr * 64   + lc4]) = qv;
        *reinterpret_cast<float4*>(&ks[hh][lr * STRK + lc4]) = kv;
        *reinterpret_cast<float4*>(&vs[hh][lr * 64   + lc4]) = vv;
    }

    const int r = tid >> 4;     // logit row
    const int c = tid & 15;     // logit col

    // ---- Dropout mask (partitionable threefry): one call per mask element ----
    // flat index = head*256 + r*16 + c ; x0 = hi64 = 0, x1 = flat
    const uint32_t i0 = (uint32_t)h0 * 256u + (uint32_t)(r * 16 + c);
    const uint32_t i1 = i0 + (uint32_t)HALF_HEADS * 256u;
    const bool keep[2] = { tf_uniform(threefry2x32_xor_k042(0u, i0)) < 0.7f,
                           tf_uniform(threefry2x32_xor_k042(0u, i1)) < 0.7f };

    __syncthreads();

    // ---- QK^T, softmax, dropout for both heads ----
    const float SCALE = 0.35355339059327373f;   // 1/sqrt(8)
    #pragma unroll
    for (int hh = 0; hh < 2; hh++) {
        float acc = 0.0f;
        #pragma unroll
        for (int dd = 0; dd < 16; dd++) {
            float4 qv = *reinterpret_cast<const float4*>(&qs[hh][r * 64   + dd * 4]);
            float4 kv = *reinterpret_cast<const float4*>(&ks[hh][c * STRK + dd * 4]);
            acc = fmaf(qv.x, kv.x, acc);
            acc = fmaf(qv.y, kv.y, acc);
            acc = fmaf(qv.z, kv.z, acc);
            acc = fmaf(qv.w, kv.w, acc);
        }
        float val = acc * SCALE + 1.0f;   // additive ones mask (cancels in softmax)

        // row-wise softmax across the 16 lanes sharing this row (within-warp groups)
        float m = val;
        #pragma unroll
        for (int s = 8; s; s >>= 1)
            m = fmaxf(m, __shfl_xor_sync(0xffffffffu, m, s));
        float e = __expf(val - m);
        float sum = e;
        #pragma unroll
        for (int s = 8; s; s >>= 1)
            sum += __shfl_xor_sync(0xffffffffu, sum, s);
        float p = e / sum;

        ps[hh][r * 16 + c] = keep[hh] ? p * (1.0f / 0.7f) : 0.0f;
    }
    __syncthreads();

    // ---- P @ V: each thread produces out[r][c*4 .. c*4+3] ----
    #pragma unroll
    for (int hh = 0; hh < 2; hh++) {
        float a0 = 0.f, a1 = 0.f, a2 = 0.f, a3 = 0.f;
        #pragma unroll
        for (int t = 0; t < 16; t++) {
            float pv = ps[hh][r * 16 + t];
            float4 vv = *reinterpret_cast<const float4*>(&vs[hh][t * 64 + lc4]);
            a0 = fmaf(pv, vv.x, a0);
            a1 = fmaf(pv, vv.y, a1);
            a2 = fmaf(pv, vv.z, a2);
            a3 = fmaf(pv, vv.w, a3);
        }
        const int base = (h0 + hh * HALF_HEADS) * HEAD_ELEMS;
        *reinterpret_cast<float4*>(out + base + r * 64 + lc4) = make_float4(a0, a1, a2, a3);
    }
}

extern "C" void kernel_launch(void* const* d_in, const int* in_sizes, int n_in,
                              void* d_out, int out_size) {
    const float* q = (const float*)d_in[0];
    const float* k = (const float*)d_in[1];
    const float* v = (const float*)d_in[2];
    float* out = (float*)d_out;
    (void)in_sizes; (void)n_in; (void)out_size;
    attn_drop_kernel<<<HALF_HEADS, 256>>>(q, k, v, out);
}

// round 6
// speedup vs baseline: 1.4247x; 1.4247x over previous
#include <cuda_runtime.h>
#include <stdint.h>

// Attention: B=256,H=32,S=16,D=64. scale=1/sqrt(8). +ones mask (cancels in softmax).
// Dropout p=0.3 replicating jax partitionable threefry (verified R5):
//   bits[i] = out0 ^ out1 of threefry2x32(key=(0,42), x0=0, x1=i)
//   uniform = bitcast((bits>>9)|0x3f800000)-1 ; keep = uniform < 0.7f.
//
// One warp per head. lane = (r = lane>>1, half = lane&1).
// Lane computes logits[r][2j+half] (j=0..7) and out[r][(2u+half)*4 ..] (u=0..7).
// Smem tiles swizzled: chunk c4 of row stored at slot row*16 + ((c4+row)&15)
// -> every k/v inner LDS.128 has 2 distinct addrs in distinct bank-quads (1 wavefront).

#define HEADS_PER_BLOCK 4
#define NBLOCKS         2048        // 8192 heads / 4

__device__ __forceinline__ uint32_t threefry2x32_xor_k042(uint32_t x0, uint32_t x1) {
    const uint32_t k0 = 0u;
    const uint32_t k1 = 42u;
    const uint32_t k2 = 0x1BD11BDAu ^ k0 ^ k1;
    x0 += k0; x1 += k1;
#define TF_R(R) { x0 += x1; x1 = __funnelshift_l(x1, x1, (R)); x1 ^= x0; }
    TF_R(13) TF_R(15) TF_R(26) TF_R(6)
    x0 += k1; x1 += k2 + 1u;
    TF_R(17) TF_R(29) TF_R(16) TF_R(24)
    x0 += k2; x1 += k0 + 2u;
    TF_R(13) TF_R(15) TF_R(26) TF_R(6)
    x0 += k0; x1 += k1 + 3u;
    TF_R(17) TF_R(29) TF_R(16) TF_R(24)
    x0 += k1; x1 += k2 + 4u;
    TF_R(13) TF_R(15) TF_R(26) TF_R(6)
    x0 += k2; x1 += k0 + 5u;
#undef TF_R
    return x0 ^ x1;
}

__device__ __forceinline__ float tf_uniform(uint32_t bits) {
    return __uint_as_float((bits >> 9) | 0x3f800000u) - 1.0f;
}

__global__ __launch_bounds__(128)
void attn_drop_kernel(const float* __restrict__ q,
                      const float* __restrict__ k,
                      const float* __restrict__ v,
                      float* __restrict__ out) {
    // 4 heads * 256 float4 slots each, per tensor: 3 * 16KB = 48KB static smem.
    __shared__ float4 sq[HEADS_PER_BLOCK * 256];
    __shared__ float4 sk[HEADS_PER_BLOCK * 256];
    __shared__ float4 sv[HEADS_PER_BLOCK * 256];

    const int tid  = threadIdx.x;
    const int w    = tid >> 5;            // warp id = head slot within block
    const int lane = tid & 31;
    const int hd   = blockIdx.x * HEADS_PER_BLOCK + w;
    const int hb   = w * 256;             // smem f4 base for this head

    const float4* qg = reinterpret_cast<const float4*>(q) + (size_t)hd * 256;
    const float4* kg = reinterpret_cast<const float4*>(k) + (size_t)hd * 256;
    const float4* vg = reinterpret_cast<const float4*>(v) + (size_t)hd * 256;

    // ---- Per-warp coalesced load of this head's q,k,v into swizzled smem ----
    #pragma unroll
    for (int i = 0; i < 8; i++) {
        const int f    = i * 32 + lane;           // f4 index within head
        const int row  = f >> 4;
        const int c4   = f & 15;
        const int slot = hb + row * 16 + ((c4 + row) & 15);
        sq[slot] = qg[f];
        sk[slot] = kg[f];
        sv[slot] = vg[f];
    }

    const int r    = lane >> 1;
    const int half = lane & 1;

    // ---- Dropout mask (overlaps LDG latency): 8 threefry calls per lane ----
    unsigned kmask = 0;
    const uint32_t fbase = (uint32_t)hd * 256u + (uint32_t)(r * 16 + half);
    #pragma unroll
    for (int j = 0; j < 8; j++) {
        uint32_t bits = threefry2x32_xor_k042(0u, fbase + 2u * (uint32_t)j);
        kmask |= (tf_uniform(bits) < 0.7f) ? (1u << j) : 0u;
    }

    __syncwarp();

    // ---- QK^T: lane computes logits[r][2j+half], j=0..7 ----
    const float SCALE = 0.35355339059327373f;     // 1/sqrt(8)
    float acc[8];
    #pragma unroll
    for (int j = 0; j < 8; j++) acc[j] = 0.0f;

    #pragma unroll
    for (int dd = 0; dd < 16; dd++) {
        const float4 qc = sq[hb + r * 16 + ((dd + r) & 15)];
        #pragma unroll
        for (int j = 0; j < 8; j++) {
            const int kr = 2 * j + half;
            const float4 kc = sk[hb + kr * 16 + ((dd + kr) & 15)];
            acc[j] = fmaf(qc.x, kc.x,
                     fmaf(qc.y, kc.y,
                     fmaf(qc.z, kc.z,
                     fmaf(qc.w, kc.w, acc[j]))));
        }
    }

    // ---- softmax over the full row (this lane + partner lane^1) ----
    float m = -1e30f;
    #pragma unroll
    for (int j = 0; j < 8; j++) {
        acc[j] = acc[j] * SCALE + 1.0f;           // additive ones mask
        m = fmaxf(m, acc[j]);
    }
    m = fmaxf(m, __shfl_xor_sync(0xffffffffu, m, 1));

    float s = 0.0f;
    #pragma unroll
    for (int j = 0; j < 8; j++) {
        acc[j] = __expf(acc[j] - m);
        s += acc[j];
    }
    s += __shfl_xor_sync(0xffffffffu, s, 1);
    const float inv = 1.0f / (s * 0.7f);          // softmax normalize + dropout scale

    float pm[8];
    #pragma unroll
    for (int j = 0; j < 8; j++)
        pm[j] = (kmask & (1u << j)) ? acc[j] * inv : 0.0f;

    // partner's 8 probabilities (other column parity)
    float po[8];
    #pragma unroll
    for (int j = 0; j < 8; j++)
        po[j] = __shfl_xor_sync(0xffffffffu, pm[j], 1);

    // ---- P @ V: lane accumulates out[r][(2u+half)*4 .. +3], u=0..7 ----
    float4 o[8];
    #pragma unroll
    for (int u = 0; u < 8; u++) o[u] = make_float4(0.f, 0.f, 0.f, 0.f);

    #pragma unroll
    for (int t = 0; t < 16; t++) {
        const float pv = ((t & 1) == half) ? pm[t >> 1] : po[t >> 1];
        #pragma unroll
        for (int u = 0; u < 8; u++) {
            const int cc = 2 * u + half;
            const float4 vc = sv[hb + t * 16 + ((cc + t) & 15)];
            o[u].x = fmaf(pv, vc.x, o[u].x);
            o[u].y = fmaf(pv, vc.y, o[u].y);
            o[u].z = fmaf(pv, vc.z, o[u].z);
            o[u].w = fmaf(pv, vc.w, o[u].w);
        }
    }

    // ---- store: lane pair covers full 32B sectors (no write amplification) ----
    float4* og = reinterpret_cast<float4*>(out) + (size_t)hd * 256 + r * 16;
    #pragma unroll
    for (int u = 0; u < 8; u++)
        og[2 * u + half] = o[u];
}

extern "C" void kernel_launch(void* const* d_in, const int* in_sizes, int n_in,
                              void* d_out, int out_size) {
    const float* q = (const float*)d_in[0];
    const float* k = (const float*)d_in[1];
    const float* v = (const float*)d_in[2];
    float* out = (float*)d_out;
    (void)in_sizes; (void)n_in; (void)out_size;
    attn_drop_kernel<<<NBLOCKS, 128>>>(q, k, v, out);
}